// round 1
// baseline (speedup 1.0000x reference)
#include <cuda_runtime.h>
#include <math.h>

#define BATCH 256
#define SEQT  128
#define INP   512
#define HID   1024
#define NOUT  32
#define NG    4096   // 4 * HID, interleaved gates: n = 4*j + g, g: 0=i,1=f,2=cell,3=o

// ---------------- scratch (device globals; no cudaMalloc allowed) ----------------
__device__ float g_gx[(size_t)BATCH * SEQT * NG];   // input-proj preactivations + biases (512MB)
__device__ float g_xr[(size_t)BATCH * SEQT * INP];  // tf32-rounded inputs
__device__ float g_wi[(size_t)NG * INP];            // packed+rounded input weights
__device__ float g_wh[(size_t)NG * HID];            // packed+rounded hidden weights
__device__ float g_bias[NG];                        // b_i* + b_h*
__device__ float g_h[2][BATCH * HID];               // double-buffered hidden state (tf32-rounded)
__device__ float g_c[BATCH * HID];                  // cell state (fp32)

// ---------------- helpers ----------------
__device__ __forceinline__ float tf32r(float x) {
    unsigned u;
    asm("cvt.rna.tf32.f32 %0, %1;" : "=r"(u) : "f"(x));
    return __uint_as_float(u);
}

__device__ __forceinline__ void cp16(float* dst, const float* src) {
    unsigned d = (unsigned)__cvta_generic_to_shared(dst);
    asm volatile("cp.async.cg.shared.global [%0], [%1], 16;" :: "r"(d), "l"(src));
}
__device__ __forceinline__ void cpcommit() { asm volatile("cp.async.commit_group;"); }
__device__ __forceinline__ void cpwait0()  { asm volatile("cp.async.wait_group 0;"); }
__device__ __forceinline__ void cpwait1()  { asm volatile("cp.async.wait_group 1;"); }

#define MMA_TF32(acc, a, b)                                                          \
    asm volatile(                                                                    \
        "mma.sync.aligned.m16n8k8.row.col.f32.tf32.tf32.f32 "                        \
        "{%0,%1,%2,%3},{%4,%5,%6,%7},{%8,%9},{%0,%1,%2,%3};"                         \
        : "+f"(acc[0]), "+f"(acc[1]), "+f"(acc[2]), "+f"(acc[3])                     \
        : "r"(a[0]), "r"(a[1]), "r"(a[2]), "r"(a[3]), "r"(b[0]), "r"(b[1]))

// ---------------- prep kernels ----------------
__global__ void k_round_x(const float* __restrict__ x) {
    size_t i = (size_t)blockIdx.x * blockDim.x + threadIdx.x;
    if (i < (size_t)BATCH * SEQT * INP) g_xr[i] = tf32r(x[i]);
}

__global__ void k_pack_wi(const float* __restrict__ wii, const float* __restrict__ wif,
                          const float* __restrict__ wic, const float* __restrict__ wio) {
    size_t i = (size_t)blockIdx.x * blockDim.x + threadIdx.x;
    if (i >= (size_t)NG * INP) return;
    int n = (int)(i / INP), k = (int)(i % INP);
    int g = n & 3, j = n >> 2;
    const float* w = (g == 0) ? wii : (g == 1) ? wif : (g == 2) ? wic : wio;
    g_wi[i] = tf32r(w[(size_t)j * INP + k]);
}

__global__ void k_pack_wh(const float* __restrict__ whi, const float* __restrict__ whf,
                          const float* __restrict__ whc, const float* __restrict__ who) {
    size_t i = (size_t)blockIdx.x * blockDim.x + threadIdx.x;
    if (i >= (size_t)NG * HID) return;
    int n = (int)(i / HID), k = (int)(i % HID);
    int g = n & 3, j = n >> 2;
    const float* w = (g == 0) ? whi : (g == 1) ? whf : (g == 2) ? whc : who;
    g_wh[i] = tf32r(w[(size_t)j * HID + k]);
}

__global__ void k_bias(const float* bii, const float* bhi, const float* bif, const float* bhf,
                       const float* bic, const float* bhc, const float* bio, const float* bho) {
    int n = blockIdx.x * blockDim.x + threadIdx.x;
    if (n >= NG) return;
    int g = n & 3, j = n >> 2;
    float v;
    if (g == 0)      v = bii[j] + bhi[j];
    else if (g == 1) v = bif[j] + bhf[j];
    else if (g == 2) v = bic[j] + bhc[j];
    else             v = bio[j] + bho[j];
    g_bias[n] = v;
}

__global__ void k_zero() {
    int i = blockIdx.x * blockDim.x + threadIdx.x;
    if (i < BATCH * HID) { g_h[0][i] = 0.f; g_c[i] = 0.f; }
}

// ---------------- GEMM core ----------------
// C-tile 128(M) x 64(N), BK=32, 8 warps (4m x 2n), warp tile 32x32 = 2x4 m16n8 frags.
// Smem: padded stride 36 floats (conflict-free frag loads), double-buffered cp.async.
// Stage layout: [A(128x36)][B(64x36)] per stage; stage stride 6912 floats; total 55296B.
static const int SMEM_BYTES = 55296;

template <int K>
__device__ __forceinline__ void gemm_tiles(const float* __restrict__ A, const float* __restrict__ B,
                                           int m0, int n0, float* smem, float acc[2][4][4]) {
    const int tid = threadIdx.x;
    const int lane = tid & 31, warp = tid >> 5;
    const int wm = warp & 3, wn = warp >> 2;
    const int lr = lane >> 2, lc = lane & 3;

    float* As[2] = { smem,        smem + 6912 };
    float* Bs[2] = { smem + 4608, smem + 4608 + 6912 };

#pragma unroll
    for (int mi = 0; mi < 2; mi++)
#pragma unroll
        for (int ni = 0; ni < 4; ni++)
#pragma unroll
            for (int q = 0; q < 4; q++) acc[mi][ni][q] = 0.f;

    auto load_stage = [&](int st, int k0) {
#pragma unroll
        for (int i = 0; i < 4; i++) {                   // A: 128x32 = 1024 float4
            int q = i * 256 + tid; int r = q >> 3, c = q & 7;
            cp16(As[st] + r * 36 + c * 4, A + (size_t)(m0 + r) * K + k0 + c * 4);
        }
#pragma unroll
        for (int i = 0; i < 2; i++) {                   // B: 64x32 = 512 float4
            int q = i * 256 + tid; int r = q >> 3, c = q & 7;
            cp16(Bs[st] + r * 36 + c * 4, B + (size_t)(n0 + r) * K + k0 + c * 4);
        }
    };

    const int KT = K / 32;
    load_stage(0, 0);
    cpcommit();

    for (int kt = 0; kt < KT; kt++) {
        if (kt + 1 < KT) { load_stage((kt + 1) & 1, (kt + 1) * 32); cpcommit(); cpwait1(); }
        else             { cpwait0(); }
        __syncthreads();

        const float* as = As[kt & 1];
        const float* bs = Bs[kt & 1];
#pragma unroll
        for (int k8 = 0; k8 < 4; k8++) {
            const int ko = k8 * 8;
            unsigned af[2][4];
#pragma unroll
            for (int mi = 0; mi < 2; mi++) {
                int rb = wm * 32 + mi * 16 + lr;
                af[mi][0] = __float_as_uint(as[rb * 36 + ko + lc]);
                af[mi][1] = __float_as_uint(as[(rb + 8) * 36 + ko + lc]);
                af[mi][2] = __float_as_uint(as[rb * 36 + ko + lc + 4]);
                af[mi][3] = __float_as_uint(as[(rb + 8) * 36 + ko + lc + 4]);
            }
            unsigned bf[4][2];
#pragma unroll
            for (int ni = 0; ni < 4; ni++) {
                int nb = wn * 32 + ni * 8 + lr;
                bf[ni][0] = __float_as_uint(bs[nb * 36 + ko + lc]);
                bf[ni][1] = __float_as_uint(bs[nb * 36 + ko + lc + 4]);
            }
#pragma unroll
            for (int mi = 0; mi < 2; mi++)
#pragma unroll
                for (int ni = 0; ni < 4; ni++) MMA_TF32(acc[mi][ni], af[mi], bf[ni]);
        }
        __syncthreads();
    }
}

// ---------------- input-projection GEMM: g_gx = X @ Wi^T + bias ----------------
__global__ __launch_bounds__(256) void k_gemm_x() {
    extern __shared__ float smem[];
    const int n0 = blockIdx.x * 64;
    const int m0 = blockIdx.y * 128;
    float acc[2][4][4];
    gemm_tiles<INP>(g_xr, g_wi, m0, n0, smem, acc);

    const int lane = threadIdx.x & 31, warp = threadIdx.x >> 5;
    const int wm = warp & 3, wn = warp >> 2;
    const int lr = lane >> 2, lc = lane & 3;
#pragma unroll
    for (int mi = 0; mi < 2; mi++)
#pragma unroll
        for (int ni = 0; ni < 4; ni++) {
            int r = wm * 32 + mi * 16 + lr;
            int cc = wn * 32 + ni * 8 + 2 * lc;
            int n = n0 + cc;
            float b0 = g_bias[n], b1 = g_bias[n + 1];
            float2 v0 = { acc[mi][ni][0] + b0, acc[mi][ni][1] + b1 };
            float2 v1 = { acc[mi][ni][2] + b0, acc[mi][ni][3] + b1 };
            *reinterpret_cast<float2*>(&g_gx[(size_t)(m0 + r) * NG + n])     = v0;
            *reinterpret_cast<float2*>(&g_gx[(size_t)(m0 + r + 8) * NG + n]) = v1;
        }
}

// ---------------- per-timestep: pre = h@Wh^T + gx[t]; fused LSTM elementwise ----------------
__global__ __launch_bounds__(256) void k_step(int t) {
    extern __shared__ float smem[];
    const int n0 = blockIdx.x * 64;   // 64 interleaved cols = 16 hidden units x 4 gates
    const int m0 = blockIdx.y * 128;  // batch rows
    const float* hin = g_h[t & 1];
    float* hout = g_h[(t + 1) & 1];

    float acc[2][4][4];
    gemm_tiles<HID>(hin, g_wh, m0, n0, smem, acc);
    __syncthreads();  // done with mainloop buffers; reuse smem for the pre-tile

    // scatter accum fragments -> smem tile [128][64], stride 65
    const int lane = threadIdx.x & 31, warp = threadIdx.x >> 5;
    const int wm = warp & 3, wn = warp >> 2;
    const int lr = lane >> 2, lc = lane & 3;
#pragma unroll
    for (int mi = 0; mi < 2; mi++)
#pragma unroll
        for (int ni = 0; ni < 4; ni++) {
            int r = wm * 32 + mi * 16 + lr;
            int cc = wn * 32 + ni * 8 + 2 * lc;
            smem[r * 65 + cc]           = acc[mi][ni][0];
            smem[r * 65 + cc + 1]       = acc[mi][ni][1];
            smem[(r + 8) * 65 + cc]     = acc[mi][ni][2];
            smem[(r + 8) * 65 + cc + 1] = acc[mi][ni][3];
        }
    __syncthreads();

    // 128 rows x 16 hidden units = 2048 (b,j) pairs; 8 per thread
#pragma unroll
    for (int s = 0; s < 8; s++) {
        int p = s * 256 + threadIdx.x;
        int r = p >> 4, jj = p & 15;
        int b = m0 + r;
        size_t gxo = ((size_t)b * SEQT + t) * NG + n0 + 4 * jj;
        float p0 = smem[r * 65 + 4 * jj + 0] + g_gx[gxo + 0];
        float p1 = smem[r * 65 + 4 * jj + 1] + g_gx[gxo + 1];
        float p2 = smem[r * 65 + 4 * jj + 2] + g_gx[gxo + 2];
        float p3 = smem[r * 65 + 4 * jj + 3] + g_gx[gxo + 3];
        float ig = 1.f / (1.f + expf(-p0));
        float fg = 1.f / (1.f + expf(-p1));
        float gg = tanhf(p2);
        float og = 1.f / (1.f + expf(-p3));
        int hidx = b * HID + (n0 >> 2) + jj;
        float cn = fg * g_c[hidx] + ig * gg;
        g_c[hidx] = cn;
        hout[hidx] = tf32r(og * tanhf(cn));
    }
}

// ---------------- final FC + log_softmax ----------------
__global__ void k_final(const float* __restrict__ wfc, float* __restrict__ out) {
    __shared__ float hs[HID];
    __shared__ float logits[NOUT];
    const int b = blockIdx.x, tid = threadIdx.x;
    const float* h = g_h[0];  // t=127 wrote buffer (128 & 1) == 0
    for (int i = tid; i < HID; i += 256) hs[i] = h[b * HID + i];
    __syncthreads();

    const int warp = tid >> 5, lane = tid & 31;
#pragma unroll
    for (int oo = 0; oo < 4; oo++) {
        int o = warp * 4 + oo;
        float s = 0.f;
        for (int k = lane; k < HID; k += 32) s += hs[k] * wfc[o * HID + k];
#pragma unroll
        for (int off = 16; off; off >>= 1) s += __shfl_xor_sync(0xffffffffu, s, off);
        if (lane == 0) logits[o] = s;
    }
    __syncthreads();

    if (tid < 32) {
        float l = logits[tid];
        float m = l;
#pragma unroll
        for (int off = 16; off; off >>= 1) m = fmaxf(m, __shfl_xor_sync(0xffffffffu, m, off));
        float e = expf(l - m);
        float se = e;
#pragma unroll
        for (int off = 16; off; off >>= 1) se += __shfl_xor_sync(0xffffffffu, se, off);
        out[b * NOUT + tid] = l - m - logf(se);
    }
}

// ---------------- launch ----------------
extern "C" void kernel_launch(void* const* d_in, const int* in_sizes, int n_in,
                              void* d_out, int out_size) {
    const float* x    = (const float*)d_in[0];
    const float* w_ii = (const float*)d_in[1];
    const float* w_hi = (const float*)d_in[2];
    const float* b_ii = (const float*)d_in[3];
    const float* b_hi = (const float*)d_in[4];
    const float* w_if = (const float*)d_in[5];
    const float* w_hf = (const float*)d_in[6];
    const float* b_if = (const float*)d_in[7];
    const float* b_hf = (const float*)d_in[8];
    const float* w_io = (const float*)d_in[9];
    const float* w_ho = (const float*)d_in[10];
    const float* b_io = (const float*)d_in[11];
    const float* b_ho = (const float*)d_in[12];
    const float* w_ic = (const float*)d_in[13];
    const float* w_hc = (const float*)d_in[14];
    const float* b_ic = (const float*)d_in[15];
    const float* b_hc = (const float*)d_in[16];
    const float* w_fc = (const float*)d_in[17];

    cudaFuncSetAttribute(k_gemm_x, cudaFuncAttributeMaxDynamicSharedMemorySize, SMEM_BYTES);
    cudaFuncSetAttribute(k_step,   cudaFuncAttributeMaxDynamicSharedMemorySize, SMEM_BYTES);

    k_round_x<<<65536, 256>>>(x);
    k_pack_wi<<<8192, 256>>>(w_ii, w_if, w_ic, w_io);
    k_pack_wh<<<16384, 256>>>(w_hi, w_hf, w_hc, w_ho);
    k_bias<<<16, 256>>>(b_ii, b_hi, b_if, b_hf, b_ic, b_hc, b_io, b_ho);
    k_zero<<<1024, 256>>>();

    k_gemm_x<<<dim3(64, 256), 256, SMEM_BYTES>>>();

    for (int t = 0; t < SEQT; t++)
        k_step<<<dim3(64, 2), 256, SMEM_BYTES>>>(t);

    k_final<<<BATCH, 256>>>(w_fc, (float*)d_out);
}

// round 3
// speedup vs baseline: 1.7954x; 1.7954x over previous
#include <cuda_runtime.h>
#include <cuda_bf16.h>
#include <cstdint>
#include <math.h>

#define BATCH 256
#define SEQT  128
#define INP   512
#define HID   1024
#define NOUT  32
#define NG    4096   // 4*HID, interleaved gates: n = 4*j + g (0=i,1=f,2=cell,3=o)

// ---------------- scratch (device globals; no cudaMalloc allowed) ----------------
__device__ float         g_gx[(size_t)BATCH * SEQT * NG];    // input-proj preacts + bias (fp32)
__device__ __nv_bfloat16 g_xr[(size_t)BATCH * SEQT * INP];   // bf16 inputs
__device__ __nv_bfloat16 g_wi[(size_t)NG * INP];             // packed bf16 input weights
__device__ __nv_bfloat16 g_wh[(size_t)NG * HID];             // packed bf16 hidden weights
__device__ float         g_bias[NG];
__device__ __nv_bfloat16 g_h[2][BATCH * HID];                // double-buffered hidden state (bf16)
__device__ float         g_c[BATCH * HID];                   // cell state fp32 [b][j]

// ---------------- helpers ----------------
__device__ __forceinline__ uint32_t smem_u32(const void* p) {
    return (uint32_t)__cvta_generic_to_shared(p);
}
__device__ __forceinline__ void cp16s(uint32_t dst, const void* src) {
    asm volatile("cp.async.cg.shared.global [%0], [%1], 16;" :: "r"(dst), "l"(src));
}
#define CP_COMMIT() asm volatile("cp.async.commit_group;" ::: "memory")
#define CP_WAIT0()  asm volatile("cp.async.wait_group 0;" ::: "memory")
#define CP_WAIT1()  asm volatile("cp.async.wait_group 1;" ::: "memory")

// smem layout: 64B rows (BK=32 bf16), 16B chunk swizzle conflict-free for
// cp.async writes AND ldmatrix 8-row column reads.
__device__ __forceinline__ uint32_t sw(int row, int c) {
    return (uint32_t)(row * 64 + ((c ^ ((row >> 1) & 3)) << 4));
}

__device__ __forceinline__ void ldsm4(uint32_t& r0, uint32_t& r1, uint32_t& r2, uint32_t& r3,
                                      uint32_t addr) {
    asm volatile("ldmatrix.sync.aligned.m8n8.x4.shared.b16 {%0,%1,%2,%3}, [%4];"
                 : "=r"(r0), "=r"(r1), "=r"(r2), "=r"(r3) : "r"(addr));
}

#define MMA_BF16(acc, a, b)                                                          \
    asm volatile(                                                                    \
        "mma.sync.aligned.m16n8k16.row.col.f32.bf16.bf16.f32 "                       \
        "{%0,%1,%2,%3},{%4,%5,%6,%7},{%8,%9},{%0,%1,%2,%3};"                         \
        : "+f"(acc[0]), "+f"(acc[1]), "+f"(acc[2]), "+f"(acc[3])                     \
        : "r"(a[0]), "r"(a[1]), "r"(a[2]), "r"(a[3]), "r"(b[0]), "r"(b[1]))

// ---------------- prep kernels ----------------
__global__ void k_round_x(const float* __restrict__ x) {
    size_t i = (size_t)blockIdx.x * blockDim.x + threadIdx.x;
    if (i < (size_t)BATCH * SEQT * INP) g_xr[i] = __float2bfloat16_rn(x[i]);
}
__global__ void k_pack_wi(const float* __restrict__ wii, const float* __restrict__ wif,
                          const float* __restrict__ wic, const float* __restrict__ wio) {
    size_t i = (size_t)blockIdx.x * blockDim.x + threadIdx.x;
    if (i >= (size_t)NG * INP) return;
    int n = (int)(i / INP), k = (int)(i % INP);
    int g = n & 3, j = n >> 2;
    const float* w = (g == 0) ? wii : (g == 1) ? wif : (g == 2) ? wic : wio;
    g_wi[i] = __float2bfloat16_rn(w[(size_t)j * INP + k]);
}
__global__ void k_pack_wh(const float* __restrict__ whi, const float* __restrict__ whf,
                          const float* __restrict__ whc, const float* __restrict__ who) {
    size_t i = (size_t)blockIdx.x * blockDim.x + threadIdx.x;
    if (i >= (size_t)NG * HID) return;
    int n = (int)(i / HID), k = (int)(i % HID);
    int g = n & 3, j = n >> 2;
    const float* w = (g == 0) ? whi : (g == 1) ? whf : (g == 2) ? whc : who;
    g_wh[i] = __float2bfloat16_rn(w[(size_t)j * HID + k]);
}
__global__ void k_bias(const float* bii, const float* bhi, const float* bif, const float* bhf,
                       const float* bic, const float* bhc, const float* bio, const float* bho) {
    int n = blockIdx.x * blockDim.x + threadIdx.x;
    if (n >= NG) return;
    int g = n & 3, j = n >> 2;
    float v;
    if (g == 0)      v = bii[j] + bhi[j];
    else if (g == 1) v = bif[j] + bhf[j];
    else if (g == 2) v = bic[j] + bhc[j];
    else             v = bio[j] + bho[j];
    g_bias[n] = v;
}
__global__ void k_zero() {
    int i = blockIdx.x * blockDim.x + threadIdx.x;
    if (i < BATCH * HID) { g_h[0][i] = __float2bfloat16_rn(0.f); g_c[i] = 0.f; }
}

// ============================================================================
// Input GEMM: g_gx[32768 x 4096] = Xr @ Wi^T + bias   (bf16 mma, fp32 accum)
// CTA tile 128(M) x 128(N), K=512, BK=32, 2-stage cp.async.
// 8 warps as 4m x 2n; warp tile 32x64 (mi=2, ni=8). Grid (32 n, 256 m).
// Stage = A 8KB + B 8KB; 2 stages = 32KB.
// ============================================================================
static const int X_SMEM = 32768;

__global__ __launch_bounds__(256, 1) void k_gemm_x() {
    extern __shared__ char smem[];
    const uint32_t sb = smem_u32(smem);
    const int tid = threadIdx.x, lane = tid & 31, wid = tid >> 5;
    const int wm = wid & 3, wn = wid >> 2;
    const int n0 = blockIdx.x * 128, m0 = blockIdx.y * 128;

    float acc[2][8][4];
#pragma unroll
    for (int mi = 0; mi < 2; mi++)
#pragma unroll
        for (int ni = 0; ni < 8; ni++)
#pragma unroll
            for (int q = 0; q < 4; q++) acc[mi][ni][q] = 0.f;

    auto load_slab = [&](int s) {
        const uint32_t ab = sb + (uint32_t)(s & 1) * 16384u;
        const int k0 = s * 32;
#pragma unroll
        for (int i = 0; i < 2; i++) {      // A: 128 rows x 4 chunks
            int q = tid + i * 256, row = q >> 2, c = q & 3;
            cp16s(ab + sw(row, c), g_xr + (size_t)(m0 + row) * INP + k0 + c * 8);
        }
#pragma unroll
        for (int i = 0; i < 2; i++) {      // B: 128 rows x 4 chunks
            int q = tid + i * 256, row = q >> 2, c = q & 3;
            cp16s(ab + 8192u + sw(row, c), g_wi + (size_t)(n0 + row) * INP + k0 + c * 8);
        }
    };

    const int KT = INP / 32;
    load_slab(0); CP_COMMIT();
    for (int kt = 0; kt < KT; kt++) {
        if (kt + 1 < KT) { load_slab(kt + 1); CP_COMMIT(); CP_WAIT1(); }
        else             { CP_WAIT0(); }
        __syncthreads();
        const uint32_t ab = sb + (uint32_t)(kt & 1) * 16384u;
        const uint32_t bb = ab + 8192u;
#pragma unroll
        for (int ks = 0; ks < 2; ks++) {
            uint32_t a[2][4];
#pragma unroll
            for (int mi = 0; mi < 2; mi++) {
                int row = wm * 32 + mi * 16 + (lane & 15);
                int c = 2 * ks + (lane >> 4);
                ldsm4(a[mi][0], a[mi][1], a[mi][2], a[mi][3], ab + sw(row, c));
            }
            uint32_t b[8][2];
#pragma unroll
            for (int nt = 0; nt < 4; nt++) {
                int row = wn * 64 + nt * 16 + ((lane >> 4) << 3) + (lane & 7);
                int c = 2 * ks + ((lane >> 3) & 1);
                ldsm4(b[2 * nt][0], b[2 * nt][1], b[2 * nt + 1][0], b[2 * nt + 1][1],
                      bb + sw(row, c));
            }
#pragma unroll
            for (int mi = 0; mi < 2; mi++)
#pragma unroll
                for (int ni = 0; ni < 8; ni++) MMA_BF16(acc[mi][ni], a[mi], b[ni]);
        }
        __syncthreads();
    }

    const int lr = lane >> 2, lc = lane & 3;
#pragma unroll
    for (int mi = 0; mi < 2; mi++)
#pragma unroll
        for (int ni = 0; ni < 8; ni++) {
            int r = wm * 32 + mi * 16 + lr;
            int cc = wn * 64 + ni * 8 + 2 * lc;
            int n = n0 + cc;
            float b0 = g_bias[n], b1 = g_bias[n + 1];
            float2 v0 = { acc[mi][ni][0] + b0, acc[mi][ni][1] + b1 };
            float2 v1 = { acc[mi][ni][2] + b0, acc[mi][ni][3] + b1 };
            *reinterpret_cast<float2*>(&g_gx[(size_t)(m0 + r) * NG + n])     = v0;
            *reinterpret_cast<float2*>(&g_gx[(size_t)(m0 + r + 8) * NG + n]) = v1;
        }
}

// ============================================================================
// Step kernel: pre = h @ Wh^T + gx[t]; fused LSTM elementwise.
// CTA tile 128(M) x 64(N), K=1024, BK=32, 2-stage cp.async.
// 8 warps as 4m x 2n; warp tile 32x32 (mi=2, ni=4). Grid (64 n, 2 m) = 128 CTAs.
// Stage = A 8KB + B 4KB; 2 stages = 24KB. Epilogue smem tile 128x65 fp32 = 33280B.
// ============================================================================
static const int S_SMEM = 33280;

__global__ __launch_bounds__(256, 1) void k_step(int t) {
    extern __shared__ char smem[];
    const uint32_t sb = smem_u32(smem);
    const int tid = threadIdx.x, lane = tid & 31, wid = tid >> 5;
    const int wm = wid & 3, wn = wid >> 2;
    const int n0 = blockIdx.x * 64, m0 = blockIdx.y * 128;
    const __nv_bfloat16* __restrict__ hin = g_h[t & 1];
    __nv_bfloat16* __restrict__ hout = g_h[(t + 1) & 1];

    float acc[2][4][4];
#pragma unroll
    for (int mi = 0; mi < 2; mi++)
#pragma unroll
        for (int ni = 0; ni < 4; ni++)
#pragma unroll
            for (int q = 0; q < 4; q++) acc[mi][ni][q] = 0.f;

    auto load_slab = [&](int s) {
        const uint32_t ab = sb + (uint32_t)(s & 1) * 12288u;
        const int k0 = s * 32;
#pragma unroll
        for (int i = 0; i < 2; i++) {      // A (h): 128 rows x 4 chunks
            int q = tid + i * 256, row = q >> 2, c = q & 3;
            cp16s(ab + sw(row, c), hin + (size_t)(m0 + row) * HID + k0 + c * 8);
        }
        {                                   // B (Wh): 64 rows x 4 chunks
            int row = tid >> 2, c = tid & 3;
            cp16s(ab + 8192u + sw(row, c), g_wh + (size_t)(n0 + row) * HID + k0 + c * 8);
        }
    };

    const int KT = HID / 32;
    load_slab(0); CP_COMMIT();
    for (int kt = 0; kt < KT; kt++) {
        if (kt + 1 < KT) { load_slab(kt + 1); CP_COMMIT(); CP_WAIT1(); }
        else             { CP_WAIT0(); }
        __syncthreads();
        const uint32_t ab = sb + (uint32_t)(kt & 1) * 12288u;
        const uint32_t bb = ab + 8192u;
#pragma unroll
        for (int ks = 0; ks < 2; ks++) {
            uint32_t a[2][4];
#pragma unroll
            for (int mi = 0; mi < 2; mi++) {
                int row = wm * 32 + mi * 16 + (lane & 15);
                int c = 2 * ks + (lane >> 4);
                ldsm4(a[mi][0], a[mi][1], a[mi][2], a[mi][3], ab + sw(row, c));
            }
            uint32_t b[4][2];
#pragma unroll
            for (int nt = 0; nt < 2; nt++) {
                int row = wn * 32 + nt * 16 + ((lane >> 4) << 3) + (lane & 7);
                int c = 2 * ks + ((lane >> 3) & 1);
                ldsm4(b[2 * nt][0], b[2 * nt][1], b[2 * nt + 1][0], b[2 * nt + 1][1],
                      bb + sw(row, c));
            }
#pragma unroll
            for (int mi = 0; mi < 2; mi++)
#pragma unroll
                for (int ni = 0; ni < 4; ni++) MMA_BF16(acc[mi][ni], a[mi], b[ni]);
        }
        __syncthreads();
    }

    // scatter acc -> smem pre-tile [128][64], stride 65 fp32
    float* pre = (float*)smem;
    const int lr = lane >> 2, lc = lane & 3;
#pragma unroll
    for (int mi = 0; mi < 2; mi++)
#pragma unroll
        for (int ni = 0; ni < 4; ni++) {
            int r = wm * 32 + mi * 16 + lr;
            int cc = wn * 32 + ni * 8 + 2 * lc;
            pre[r * 65 + cc]           = acc[mi][ni][0];
            pre[r * 65 + cc + 1]       = acc[mi][ni][1];
            pre[(r + 8) * 65 + cc]     = acc[mi][ni][2];
            pre[(r + 8) * 65 + cc + 1] = acc[mi][ni][3];
        }
    __syncthreads();

    // 128 rows x 16 hidden units; 8 (b,j) pairs per thread
#pragma unroll
    for (int s = 0; s < 8; s++) {
        int p = s * 256 + tid;
        int r = p >> 4, jj = p & 15;
        int b = m0 + r;
        size_t gxo = ((size_t)b * SEQT + t) * NG + n0 + 4 * jj;
        float4 gx4 = *(const float4*)&g_gx[gxo];
        float p0 = pre[r * 65 + 4 * jj + 0] + gx4.x;
        float p1 = pre[r * 65 + 4 * jj + 1] + gx4.y;
        float p2 = pre[r * 65 + 4 * jj + 2] + gx4.z;
        float p3 = pre[r * 65 + 4 * jj + 3] + gx4.w;
        float ig = 1.f / (1.f + __expf(-p0));
        float fg = 1.f / (1.f + __expf(-p1));
        float gg = tanhf(p2);
        float og = 1.f / (1.f + __expf(-p3));
        int hidx = b * HID + (n0 >> 2) + jj;
        float cn = fg * g_c[hidx] + ig * gg;
        g_c[hidx] = cn;
        hout[hidx] = __float2bfloat16_rn(og * tanhf(cn));
    }
}

// ---------------- final FC + log_softmax ----------------
__global__ void k_final(const float* __restrict__ wfc, float* __restrict__ out) {
    __shared__ float hs[HID];
    __shared__ float logits[NOUT];
    const int b = blockIdx.x, tid = threadIdx.x;
    const __nv_bfloat16* h = g_h[0];   // t=127 wrote buffer (128 & 1) == 0
    for (int i = tid; i < HID; i += 256) hs[i] = __bfloat162float(h[b * HID + i]);
    __syncthreads();

    const int warp = tid >> 5, lane = tid & 31;
#pragma unroll
    for (int oo = 0; oo < 4; oo++) {
        int o = warp * 4 + oo;
        float s = 0.f;
        for (int k = lane; k < HID; k += 32) s += hs[k] * wfc[o * HID + k];
#pragma unroll
        for (int off = 16; off; off >>= 1) s += __shfl_xor_sync(0xffffffffu, s, off);
        if (lane == 0) logits[o] = s;
    }
    __syncthreads();

    if (tid < 32) {
        float l = logits[tid];
        float m = l;
#pragma unroll
        for (int off = 16; off; off >>= 1) m = fmaxf(m, __shfl_xor_sync(0xffffffffu, m, off));
        float e = expf(l - m);
        float se = e;
#pragma unroll
        for (int off = 16; off; off >>= 1) se += __shfl_xor_sync(0xffffffffu, se, off);
        out[b * NOUT + tid] = l - m - logf(se);
    }
}

// ---------------- launch ----------------
extern "C" void kernel_launch(void* const* d_in, const int* in_sizes, int n_in,
                              void* d_out, int out_size) {
    const float* x    = (const float*)d_in[0];
    const float* w_ii = (const float*)d_in[1];
    const float* w_hi = (const float*)d_in[2];
    const float* b_ii = (const float*)d_in[3];
    const float* b_hi = (const float*)d_in[4];
    const float* w_if = (const float*)d_in[5];
    const float* w_hf = (const float*)d_in[6];
    const float* b_if = (const float*)d_in[7];
    const float* b_hf = (const float*)d_in[8];
    const float* w_io = (const float*)d_in[9];
    const float* w_ho = (const float*)d_in[10];
    const float* b_io = (const float*)d_in[11];
    const float* b_ho = (const float*)d_in[12];
    const float* w_ic = (const float*)d_in[13];
    const float* w_hc = (const float*)d_in[14];
    const float* b_ic = (const float*)d_in[15];
    const float* b_hc = (const float*)d_in[16];
    const float* w_fc = (const float*)d_in[17];

    cudaFuncSetAttribute(k_gemm_x, cudaFuncAttributeMaxDynamicSharedMemorySize, X_SMEM);
    cudaFuncSetAttribute(k_step,   cudaFuncAttributeMaxDynamicSharedMemorySize, S_SMEM);

    k_round_x<<<65536, 256>>>(x);
    k_pack_wi<<<8192, 256>>>(w_ii, w_if, w_ic, w_io);
    k_pack_wh<<<16384, 256>>>(w_hi, w_hf, w_hc, w_ho);
    k_bias<<<16, 256>>>(b_ii, b_hi, b_if, b_hf, b_ic, b_hc, b_io, b_ho);
    k_zero<<<1024, 256>>>();

    k_gemm_x<<<dim3(32, 256), 256, X_SMEM>>>();

    for (int t = 0; t < SEQT; t++)
        k_step<<<dim3(64, 2), 256, S_SMEM>>>(t);

    k_final<<<BATCH, 256>>>(w_fc, (float*)d_out);
}

// round 4
// speedup vs baseline: 2.5411x; 1.4154x over previous
#include <cuda_runtime.h>
#include <cuda_bf16.h>
#include <cstdint>
#include <math.h>

#define BATCH 256
#define SEQT  128
#define INP   512
#define HID   1024
#define NOUT  32
#define NG    4096   // 4*HID, interleaved gates: n = 4*j + g (0=i,1=f,2=cell,3=o)

// ---------------- scratch (device globals; no cudaMalloc allowed) ----------------
__device__ float         g_gx[(size_t)BATCH * SEQT * NG];    // input-proj preacts + bias (fp32)
__device__ __nv_bfloat16 g_xr[(size_t)BATCH * SEQT * INP];   // bf16 inputs
__device__ __nv_bfloat16 g_wi[(size_t)NG * INP];             // packed bf16 input weights
__device__ __nv_bfloat16 g_wh[(size_t)NG * HID];             // packed bf16 hidden weights
__device__ float         g_bias[NG];
__device__ __nv_bfloat16 g_h[2][BATCH * HID];                // double-buffered hidden state
__device__ unsigned      g_bar;                              // grid barrier counter

// ---------------- helpers ----------------
__device__ __forceinline__ uint32_t smem_u32(const void* p) {
    return (uint32_t)__cvta_generic_to_shared(p);
}
__device__ __forceinline__ void cp16s(uint32_t dst, const void* src) {
    asm volatile("cp.async.cg.shared.global [%0], [%1], 16;" :: "r"(dst), "l"(src));
}
#define CP_COMMIT() asm volatile("cp.async.commit_group;" ::: "memory")
#define CP_WAIT0()  asm volatile("cp.async.wait_group 0;" ::: "memory")
#define CP_WAIT1()  asm volatile("cp.async.wait_group 1;" ::: "memory")

// A-stage smem layout: 64B rows (BK=32 bf16), 16B chunk swizzle.
__device__ __forceinline__ uint32_t sw(int row, int c) {
    return (uint32_t)(row * 64 + ((c ^ ((row >> 1) & 3)) << 4));
}
// Persistent Wh smem layout: 2KB rows (full K=1024 bf16), per-row chunk swizzle.
__device__ __forceinline__ uint32_t whsw(int row, int c) {
    return (uint32_t)(row * 2048 + ((c ^ (row & 7)) << 4));
}

__device__ __forceinline__ void ldsm4(uint32_t& r0, uint32_t& r1, uint32_t& r2, uint32_t& r3,
                                      uint32_t addr) {
    asm volatile("ldmatrix.sync.aligned.m8n8.x4.shared.b16 {%0,%1,%2,%3}, [%4];"
                 : "=r"(r0), "=r"(r1), "=r"(r2), "=r"(r3) : "r"(addr));
}

#define MMA_BF16(acc, a, b)                                                          \
    asm volatile(                                                                    \
        "mma.sync.aligned.m16n8k16.row.col.f32.bf16.bf16.f32 "                       \
        "{%0,%1,%2,%3},{%4,%5,%6,%7},{%8,%9},{%0,%1,%2,%3};"                         \
        : "+f"(acc[0]), "+f"(acc[1]), "+f"(acc[2]), "+f"(acc[3])                     \
        : "r"(a[0]), "r"(a[1]), "r"(a[2]), "r"(a[3]), "r"(b[0]), "r"(b[1]))

// ---------------- prep kernels ----------------
__global__ void k_round_x(const float* __restrict__ x) {
    size_t i = (size_t)blockIdx.x * blockDim.x + threadIdx.x;
    if (i < (size_t)BATCH * SEQT * INP) g_xr[i] = __float2bfloat16_rn(x[i]);
}
__global__ void k_pack_wi(const float* __restrict__ wii, const float* __restrict__ wif,
                          const float* __restrict__ wic, const float* __restrict__ wio) {
    size_t i = (size_t)blockIdx.x * blockDim.x + threadIdx.x;
    if (i >= (size_t)NG * INP) return;
    int n = (int)(i / INP), k = (int)(i % INP);
    int g = n & 3, j = n >> 2;
    const float* w = (g == 0) ? wii : (g == 1) ? wif : (g == 2) ? wic : wio;
    g_wi[i] = __float2bfloat16_rn(w[(size_t)j * INP + k]);
}
__global__ void k_pack_wh(const float* __restrict__ whi, const float* __restrict__ whf,
                          const float* __restrict__ whc, const float* __restrict__ who) {
    size_t i = (size_t)blockIdx.x * blockDim.x + threadIdx.x;
    if (i >= (size_t)NG * HID) return;
    int n = (int)(i / HID), k = (int)(i % HID);
    int g = n & 3, j = n >> 2;
    const float* w = (g == 0) ? whi : (g == 1) ? whf : (g == 2) ? whc : who;
    g_wh[i] = __float2bfloat16_rn(w[(size_t)j * HID + k]);
}
__global__ void k_bias(const float* bii, const float* bhi, const float* bif, const float* bhf,
                       const float* bic, const float* bhc, const float* bio, const float* bho) {
    int n = blockIdx.x * blockDim.x + threadIdx.x;
    if (n >= NG) return;
    int g = n & 3, j = n >> 2;
    float v;
    if (g == 0)      v = bii[j] + bhi[j];
    else if (g == 1) v = bif[j] + bhf[j];
    else if (g == 2) v = bic[j] + bhc[j];
    else             v = bio[j] + bho[j];
    g_bias[n] = v;
}
__global__ void k_zero() {
    int i = blockIdx.x * blockDim.x + threadIdx.x;
    if (i < BATCH * HID) g_h[0][i] = __float2bfloat16_rn(0.f);
    if (i == 0) g_bar = 0u;
}

// ============================================================================
// Input GEMM: g_gx[32768 x 4096] = Xr @ Wi^T + bias   (bf16 mma, fp32 accum)
// CTA tile 128 x 128, K=512, BK=32, 3-stage cp.async, ONE barrier per slab.
// 8 warps as 4m x 2n; warp tile 32x64. Grid (32 n, 256 m) = 8192 CTAs.
// Stage = A 8KB + B 8KB; 3 stages = 48KB.
// ============================================================================
static const int X_SMEM = 49152;

__global__ __launch_bounds__(256, 1) void k_gemm_x() {
    extern __shared__ char smem[];
    const uint32_t sb = smem_u32(smem);
    const int tid = threadIdx.x, lane = tid & 31, wid = tid >> 5;
    const int wm = wid & 3, wn = wid >> 2;
    const int n0 = blockIdx.x * 128, m0 = blockIdx.y * 128;

    float acc[2][8][4];
#pragma unroll
    for (int mi = 0; mi < 2; mi++)
#pragma unroll
        for (int ni = 0; ni < 8; ni++)
#pragma unroll
            for (int q = 0; q < 4; q++) acc[mi][ni][q] = 0.f;

    auto load_slab = [&](int s) {
        const uint32_t ab = sb + (uint32_t)(s % 3) * 16384u;
        const int k0 = s * 32;
#pragma unroll
        for (int i = 0; i < 2; i++) {
            int q = tid + i * 256, row = q >> 2, c = q & 3;
            cp16s(ab + sw(row, c), g_xr + (size_t)(m0 + row) * INP + k0 + c * 8);
        }
#pragma unroll
        for (int i = 0; i < 2; i++) {
            int q = tid + i * 256, row = q >> 2, c = q & 3;
            cp16s(ab + 8192u + sw(row, c), g_wi + (size_t)(n0 + row) * INP + k0 + c * 8);
        }
    };

    const int KT = INP / 32;
    load_slab(0); CP_COMMIT();
    load_slab(1); CP_COMMIT();
    for (int kt = 0; kt < KT; kt++) {
        if (kt + 1 < KT) CP_WAIT1(); else CP_WAIT0();
        __syncthreads();
        if (kt + 2 < KT) { load_slab(kt + 2); CP_COMMIT(); }
        const uint32_t ab = sb + (uint32_t)(kt % 3) * 16384u;
        const uint32_t bb = ab + 8192u;
#pragma unroll
        for (int ks = 0; ks < 2; ks++) {
            uint32_t a[2][4];
#pragma unroll
            for (int mi = 0; mi < 2; mi++) {
                int row = wm * 32 + mi * 16 + (lane & 15);
                int c = 2 * ks + (lane >> 4);
                ldsm4(a[mi][0], a[mi][1], a[mi][2], a[mi][3], ab + sw(row, c));
            }
            uint32_t b[8][2];
#pragma unroll
            for (int nt = 0; nt < 4; nt++) {
                int row = wn * 64 + nt * 16 + ((lane >> 4) << 3) + (lane & 7);
                int c = 2 * ks + ((lane >> 3) & 1);
                ldsm4(b[2 * nt][0], b[2 * nt][1], b[2 * nt + 1][0], b[2 * nt + 1][1],
                      bb + sw(row, c));
            }
#pragma unroll
            for (int mi = 0; mi < 2; mi++)
#pragma unroll
                for (int ni = 0; ni < 8; ni++) MMA_BF16(acc[mi][ni], a[mi], b[ni]);
        }
    }

    const int lr = lane >> 2, lc = lane & 3;
#pragma unroll
    for (int mi = 0; mi < 2; mi++)
#pragma unroll
        for (int ni = 0; ni < 8; ni++) {
            int r = wm * 32 + mi * 16 + lr;
            int cc = wn * 64 + ni * 8 + 2 * lc;
            int n = n0 + cc;
            float b0 = g_bias[n], b1 = g_bias[n + 1];
            float2 v0 = { acc[mi][ni][0] + b0, acc[mi][ni][1] + b1 };
            float2 v1 = { acc[mi][ni][2] + b0, acc[mi][ni][3] + b1 };
            *reinterpret_cast<float2*>(&g_gx[(size_t)(m0 + r) * NG + n])     = v0;
            *reinterpret_cast<float2*>(&g_gx[(size_t)(m0 + r + 8) * NG + n]) = v1;
        }
}

// ============================================================================
// Persistent step kernel: all 128 timesteps in ONE launch.
// Grid (64 n, 2 m) = 128 CTAs, 1/SM, all co-resident.
// Each CTA: Wh slice (64 rows x 1024) resident in smem (128KB, loaded once).
// Per step: A(h) 3-stage cp.async ring, 1 barrier/slab, fused LSTM epilogue,
// c-state in registers, grid barrier between steps.
// Smem: [0,128K) Wh | [128K,+24K) A stages | [152K+... ,+33280) pre-tile.
// ============================================================================
static const int WH_BYTES  = 131072;
static const int A_OFF     = 131072;
static const int PRE_OFF   = 131072 + 3 * 8192;
static const int S_SMEM    = PRE_OFF + 33280;   // 188928

__global__ __launch_bounds__(256, 1) void k_steps() {
    extern __shared__ char smem[];
    const uint32_t sb = smem_u32(smem);
    const int tid = threadIdx.x, lane = tid & 31, wid = tid >> 5;
    const int wm = wid & 3, wn = wid >> 2;
    const int n0 = blockIdx.x * 64, m0 = blockIdx.y * 128;

    // ---- load Wh slice (64 rows x 1024 bf16 = 128KB) into persistent smem ----
#pragma unroll
    for (int i = 0; i < 32; i++) {
        int idx = tid + i * 256;            // 8192 16B-chunks
        int row = idx >> 7, c = idx & 127;
        cp16s(sb + whsw(row, c), g_wh + (size_t)(n0 + row) * HID + c * 8);
    }
    CP_COMMIT();

    // ---- per-thread persistent cell state: 8 (b,j) pairs ----
    float creg[8];
#pragma unroll
    for (int q = 0; q < 8; q++) creg[q] = 0.f;

    float* pre = (float*)(smem + PRE_OFF);
    const int KT = HID / 32;

    for (int t = 0; t < SEQT; t++) {
        const __nv_bfloat16* __restrict__ hin = g_h[t & 1];
        __nv_bfloat16* __restrict__ hout = g_h[(t + 1) & 1];

        float acc[2][4][4];
#pragma unroll
        for (int mi = 0; mi < 2; mi++)
#pragma unroll
            for (int ni = 0; ni < 4; ni++)
#pragma unroll
                for (int q = 0; q < 4; q++) acc[mi][ni][q] = 0.f;

        auto load_slab = [&](int s) {
            const uint32_t ab = sb + A_OFF + (uint32_t)(s % 3) * 8192u;
            const int k0 = s * 32;
#pragma unroll
            for (int i = 0; i < 2; i++) {   // A: 128 rows x 4 chunks
                int q = tid + i * 256, row = q >> 2, c = q & 3;
                cp16s(ab + sw(row, c), hin + (size_t)(m0 + row) * HID + k0 + c * 8);
            }
        };

        load_slab(0); CP_COMMIT();
        load_slab(1); CP_COMMIT();
        for (int kt = 0; kt < KT; kt++) {
            if (kt + 1 < KT) CP_WAIT1(); else CP_WAIT0();
            __syncthreads();
            if (kt + 2 < KT) { load_slab(kt + 2); CP_COMMIT(); }
            const uint32_t ab = sb + A_OFF + (uint32_t)(kt % 3) * 8192u;
#pragma unroll
            for (int ks = 0; ks < 2; ks++) {
                uint32_t a[2][4];
#pragma unroll
                for (int mi = 0; mi < 2; mi++) {
                    int row = wm * 32 + mi * 16 + (lane & 15);
                    int c = 2 * ks + (lane >> 4);
                    ldsm4(a[mi][0], a[mi][1], a[mi][2], a[mi][3], ab + sw(row, c));
                }
                uint32_t b[4][2];
#pragma unroll
                for (int nt = 0; nt < 2; nt++) {
                    int row = wn * 32 + nt * 16 + ((lane >> 4) << 3) + (lane & 7);
                    int gc = kt * 4 + 2 * ks + ((lane >> 3) & 1);
                    ldsm4(b[2 * nt][0], b[2 * nt][1], b[2 * nt + 1][0], b[2 * nt + 1][1],
                          sb + whsw(row, gc));
                }
#pragma unroll
                for (int mi = 0; mi < 2; mi++)
#pragma unroll
                    for (int ni = 0; ni < 4; ni++) MMA_BF16(acc[mi][ni], a[mi], b[ni]);
            }
        }

        // scatter acc -> pre-tile [128][64], stride 65
        const int lr = lane >> 2, lc = lane & 3;
#pragma unroll
        for (int mi = 0; mi < 2; mi++)
#pragma unroll
            for (int ni = 0; ni < 4; ni++) {
                int r = wm * 32 + mi * 16 + lr;
                int cc = wn * 32 + ni * 8 + 2 * lc;
                pre[r * 65 + cc]           = acc[mi][ni][0];
                pre[r * 65 + cc + 1]       = acc[mi][ni][1];
                pre[(r + 8) * 65 + cc]     = acc[mi][ni][2];
                pre[(r + 8) * 65 + cc + 1] = acc[mi][ni][3];
            }
        __syncthreads();

        // fused LSTM elementwise: 8 (b,j) pairs per thread
#pragma unroll
        for (int s = 0; s < 8; s++) {
            int p = s * 256 + tid;
            int r = p >> 4, jj = p & 15;
            int b = m0 + r;
            size_t gxo = ((size_t)b * SEQT + t) * NG + n0 + 4 * jj;
            float4 gx4 = *(const float4*)&g_gx[gxo];
            float p0 = pre[r * 65 + 4 * jj + 0] + gx4.x;
            float p1 = pre[r * 65 + 4 * jj + 1] + gx4.y;
            float p2 = pre[r * 65 + 4 * jj + 2] + gx4.z;
            float p3 = pre[r * 65 + 4 * jj + 3] + gx4.w;
            float ig = 1.f / (1.f + __expf(-p0));
            float fg = 1.f / (1.f + __expf(-p1));
            float gg = tanhf(p2);
            float og = 1.f / (1.f + __expf(-p3));
            float cn = fg * creg[s] + ig * gg;
            creg[s] = cn;
            hout[b * HID + (n0 >> 2) + jj] = __float2bfloat16_rn(og * tanhf(cn));
        }

        // ---- grid barrier: all h writes visible before next step's loads ----
        __threadfence();
        __syncthreads();
        if (tid == 0) {
            atomicAdd(&g_bar, 1u);
            unsigned target = (unsigned)(t + 1) * 128u;
            while (*(volatile unsigned*)&g_bar < target) { }
        }
        __syncthreads();
        __threadfence();
    }
}

// ---------------- final FC + log_softmax ----------------
__global__ void k_final(const float* __restrict__ wfc, float* __restrict__ out) {
    __shared__ float hs[HID];
    __shared__ float logits[NOUT];
    const int b = blockIdx.x, tid = threadIdx.x;
    const __nv_bfloat16* h = g_h[0];   // t=127 wrote buffer (128 & 1) == 0
    for (int i = tid; i < HID; i += 256) hs[i] = __bfloat162float(h[b * HID + i]);
    __syncthreads();

    const int warp = tid >> 5, lane = tid & 31;
#pragma unroll
    for (int oo = 0; oo < 4; oo++) {
        int o = warp * 4 + oo;
        float s = 0.f;
        for (int k = lane; k < HID; k += 32) s += hs[k] * wfc[o * HID + k];
#pragma unroll
        for (int off = 16; off; off >>= 1) s += __shfl_xor_sync(0xffffffffu, s, off);
        if (lane == 0) logits[o] = s;
    }
    __syncthreads();

    if (tid < 32) {
        float l = logits[tid];
        float m = l;
#pragma unroll
        for (int off = 16; off; off >>= 1) m = fmaxf(m, __shfl_xor_sync(0xffffffffu, m, off));
        float e = expf(l - m);
        float se = e;
#pragma unroll
        for (int off = 16; off; off >>= 1) se += __shfl_xor_sync(0xffffffffu, se, off);
        out[b * NOUT + tid] = l - m - logf(se);
    }
}

// ---------------- launch ----------------
extern "C" void kernel_launch(void* const* d_in, const int* in_sizes, int n_in,
                              void* d_out, int out_size) {
    const float* x    = (const float*)d_in[0];
    const float* w_ii = (const float*)d_in[1];
    const float* w_hi = (const float*)d_in[2];
    const float* b_ii = (const float*)d_in[3];
    const float* b_hi = (const float*)d_in[4];
    const float* w_if = (const float*)d_in[5];
    const float* w_hf = (const float*)d_in[6];
    const float* b_if = (const float*)d_in[7];
    const float* b_hf = (const float*)d_in[8];
    const float* w_io = (const float*)d_in[9];
    const float* w_ho = (const float*)d_in[10];
    const float* b_io = (const float*)d_in[11];
    const float* b_ho = (const float*)d_in[12];
    const float* w_ic = (const float*)d_in[13];
    const float* w_hc = (const float*)d_in[14];
    const float* b_ic = (const float*)d_in[15];
    const float* b_hc = (const float*)d_in[16];
    const float* w_fc = (const float*)d_in[17];

    cudaFuncSetAttribute(k_gemm_x, cudaFuncAttributeMaxDynamicSharedMemorySize, X_SMEM);
    cudaFuncSetAttribute(k_steps,  cudaFuncAttributeMaxDynamicSharedMemorySize, S_SMEM);

    k_round_x<<<65536, 256>>>(x);
    k_pack_wi<<<8192, 256>>>(w_ii, w_if, w_ic, w_io);
    k_pack_wh<<<16384, 256>>>(w_hi, w_hf, w_hc, w_ho);
    k_bias<<<16, 256>>>(b_ii, b_hi, b_if, b_hf, b_ic, b_hc, b_io, b_ho);
    k_zero<<<1024, 256>>>();

    k_gemm_x<<<dim3(32, 256), 256, X_SMEM>>>();

    k_steps<<<dim3(64, 2), 256, S_SMEM>>>();

    k_final<<<BATCH, 256>>>(w_fc, (float*)d_out);
}